// round 1
// baseline (speedup 1.0000x reference)
#include <cuda_runtime.h>
#include <math.h>

// Problem constants
#define NB 4
#define NN 512
#define NC 128

// Logit scratch (no cudaMalloc allowed) — 4 MB
__device__ float g_logits[NB * NN * NN];

// Tiling
#define TM 64         // j-pairs per block
#define KC 32         // k-chunk for weight staging
#define SW_STRIDE 196 // padded weight-chunk row stride (floats), 16B-aligned rows

// Dynamic shared layout (float offsets)
#define OFF_A    0        // activations ping  [192][64]
#define OFF_B    12288    // activations pong  [192][64]  (overlaid with xj tile in prologue)
#define OFF_W    24576    // weight chunk      [32][196]
#define OFF_BIAS 30848    // bias              [192]
#define OFF_XI   31040    // x[i]              [128]
#define SMEM_FLOATS 31168 // 124,672 bytes

extern __shared__ float smem[];

__device__ __forceinline__ float lrelu(float v) { return v > 0.f ? v : 0.01f * v; }

// One MLP layer: sOut[Nout][TM] = lrelu(W[Nout][K] * sIn[K][TM] + bias)
// Per-thread microtile: 4 pairs x 8 outputs, accumulated across KC-chunks of
// SMEM-staged (transposed, padded) weights. All LDS are .128.
__device__ void run_layer(const float* __restrict__ sIn, float* __restrict__ sOut,
                          const float* __restrict__ W, const float* __restrict__ bias,
                          int K, int Nout, int tid, bool act)
{
    float* sW    = smem + OFF_W;
    float* sBias = smem + OFF_BIAS;
    for (int o = tid; o < Nout; o += 256) sBias[o] = bias[o];

    const int ntiles = (TM / 4) * (Nout / 8);
    float acc[2][32];
#pragma unroll
    for (int t = 0; t < 2; ++t)
#pragma unroll
        for (int r = 0; r < 32; ++r) acc[t][r] = 0.f;

    for (int k0 = 0; k0 < K; k0 += KC) {
        __syncthreads(); // previous chunk readers done / input ready
        // Stage weight chunk transposed: sW[kk][o] = W[o][k0+kk] (coalesced LDG)
        for (int idx = tid; idx < Nout * KC; idx += 256) {
            int o  = idx >> 5;       // / KC
            int kk = idx & (KC - 1);
            sW[kk * SW_STRIDE + o] = W[o * K + k0 + kk];
        }
        __syncthreads();
#pragma unroll
        for (int t = 0; t < 2; ++t) {
            int tile = tid + t * 256;
            if (tile < ntiles) {
                int og = tile >> 4;   // tile / (TM/4)
                int pg = tile & 15;
                const float* Ab = sIn + k0 * TM + pg * 4;
                const float* Wb = sW + og * 8;
#pragma unroll 4
                for (int kk = 0; kk < KC; ++kk) {
                    float4 a  = *(const float4*)(Ab + kk * TM);
                    float4 w0 = *(const float4*)(Wb + kk * SW_STRIDE);
                    float4 w1 = *(const float4*)(Wb + kk * SW_STRIDE + 4);
                    float av[4] = {a.x, a.y, a.z, a.w};
                    float wv[8] = {w0.x, w0.y, w0.z, w0.w, w1.x, w1.y, w1.z, w1.w};
#pragma unroll
                    for (int pp = 0; pp < 4; ++pp)
#pragma unroll
                        for (int oo = 0; oo < 8; ++oo)
                            acc[t][pp * 8 + oo] = fmaf(av[pp], wv[oo], acc[t][pp * 8 + oo]);
                }
            }
        }
    }
    __syncthreads();
    // Epilogue: bias + leaky-relu, store transposed [o][p] as float4 over p
#pragma unroll
    for (int t = 0; t < 2; ++t) {
        int tile = tid + t * 256;
        if (tile < ntiles) {
            int og = tile >> 4;
            int pg = tile & 15;
#pragma unroll
            for (int oo = 0; oo < 8; ++oo) {
                int o = og * 8 + oo;
                float bb = sBias[o];
                float4 v;
                v.x = acc[t][0 * 8 + oo] + bb;
                v.y = acc[t][1 * 8 + oo] + bb;
                v.z = acc[t][2 * 8 + oo] + bb;
                v.w = acc[t][3 * 8 + oo] + bb;
                if (act) {
                    v.x = lrelu(v.x); v.y = lrelu(v.y);
                    v.z = lrelu(v.z); v.w = lrelu(v.w);
                }
                *(float4*)(sOut + o * TM + pg * 4) = v;
            }
        }
    }
    __syncthreads();
}

__global__ void __launch_bounds__(256, 1)
logits_kernel(const float* __restrict__ x,
              const float* __restrict__ w1, const float* __restrict__ b1,
              const float* __restrict__ w2, const float* __restrict__ b2,
              const float* __restrict__ w3, const float* __restrict__ b3,
              const float* __restrict__ w4, const float* __restrict__ b4,
              const float* __restrict__ w5, const float* __restrict__ b5)
{
    int tid = threadIdx.x;
    int blk = blockIdx.x;
    int jt = blk & 7;
    int i  = (blk >> 3) & (NN - 1);
    int b  = blk >> 12;
    int j0 = jt * TM;

    float* sA  = smem + OFF_A;
    float* sB  = smem + OFF_B;
    float* sXi = smem + OFF_XI;
    float* sXj = sB; // overlay: [64][129] padded, freed before layer1 epilogue writes sB

    const float* xb = x + (size_t)b * NN * NC;
    for (int idx = tid; idx < TM * NC; idx += 256) {
        int p = idx >> 7;
        int k = idx & 127;
        sXj[p * 129 + k] = xb[(j0 + p) * NC + k];
    }
    if (tid < NC) sXi[tid] = xb[i * NC + tid];
    __syncthreads();

    // d transposed: sA[k][p] = |x_i[k] - x_j[p][k]|
    for (int idx = tid; idx < NC * TM; idx += 256) {
        int k = idx >> 6;
        int p = idx & 63;
        sA[k * TM + p] = fabsf(sXi[k] - sXj[p * 129 + k]);
    }
    __syncthreads();

    run_layer(sA, sB, w1, b1, 128, 192, tid, true);
    run_layer(sB, sA, w2, b2, 192, 192, tid, true);
    run_layer(sA, sB, w3, b3, 192,  96, tid, true);
    run_layer(sB, sA, w4, b4,  96,  96, tid, true);

    // Layer 5: 96 -> 1, no activation
    float* sW = smem + OFF_W;
    if (tid < 96) sW[tid] = w5[tid];
    __syncthreads();
    if (tid < TM) {
        float s = b5[0];
#pragma unroll 8
        for (int k = 0; k < 96; ++k)
            s = fmaf(sA[k * TM + tid], sW[k], s);
        g_logits[((size_t)b * NN + i) * NN + j0 + tid] = s;
    }
}

__global__ void __launch_bounds__(256)
softmax_kernel(float2* __restrict__ out)
{
    __shared__ float sred[8];
    __shared__ float sval;
    int row = blockIdx.x;        // b*NN + i
    int i   = row & (NN - 1);
    const float* L = g_logits + (size_t)row * NN;
    int tid  = threadIdx.x;
    int lane = tid & 31, warp = tid >> 5;

    float l0 = L[tid];
    float l1 = L[tid + 256];
    if (tid == i)        l0 -= 1e8f;
    if (tid + 256 == i)  l1 -= 1e8f;

    float m = fmaxf(l0, l1);
#pragma unroll
    for (int o = 16; o > 0; o >>= 1) m = fmaxf(m, __shfl_xor_sync(0xffffffffu, m, o));
    if (lane == 0) sred[warp] = m;
    __syncthreads();
    if (tid == 0) {
        float v = sred[0];
        for (int w = 1; w < 8; ++w) v = fmaxf(v, sred[w]);
        sval = v;
    }
    __syncthreads();
    float M  = sval;
    float e0 = expf(l0 - M);
    float e1 = expf(l1 - M);
    float s  = e0 + e1;
#pragma unroll
    for (int o = 16; o > 0; o >>= 1) s += __shfl_xor_sync(0xffffffffu, s, o);
    __syncthreads();
    if (lane == 0) sred[warp] = s;
    __syncthreads();
    if (tid == 0) {
        float v = 0.f;
        for (int w = 0; w < 8; ++w) v += sred[w];
        sval = 1.0f / v;
    }
    __syncthreads();
    float inv = sval;

    float2* o2 = out + (size_t)row * NN;
    o2[tid]       = make_float2(tid == i ? 1.f : 0.f,       e0 * inv);
    o2[tid + 256] = make_float2(tid + 256 == i ? 1.f : 0.f, e1 * inv);
}

extern "C" void kernel_launch(void* const* d_in, const int* in_sizes, int n_in,
                              void* d_out, int out_size)
{
    const float* x  = (const float*)d_in[0];
    // d_in[1] = W_id (exact identity by construction; regenerated analytically)
    const float* w1 = (const float*)d_in[2];
    const float* b1 = (const float*)d_in[3];
    const float* w2 = (const float*)d_in[4];
    const float* b2 = (const float*)d_in[5];
    const float* w3 = (const float*)d_in[6];
    const float* b3 = (const float*)d_in[7];
    const float* w4 = (const float*)d_in[8];
    const float* b4 = (const float*)d_in[9];
    const float* w5 = (const float*)d_in[10];
    const float* b5 = (const float*)d_in[11];
    float2* out = (float2*)d_out;

    size_t smem_bytes = SMEM_FLOATS * sizeof(float);
    cudaFuncSetAttribute(logits_kernel, cudaFuncAttributeMaxDynamicSharedMemorySize,
                         (int)smem_bytes);

    logits_kernel<<<NB * NN * (NN / TM), 256, smem_bytes>>>(
        x, w1, b1, w2, b2, w3, b3, w4, b4, w5, b5);
    softmax_kernel<<<NB * NN, 256>>>(out);
}

// round 3
// speedup vs baseline: 5.8549x; 5.8549x over previous
#include <cuda_runtime.h>
#include <cstdint>
#include <math.h>

#define NB 4
#define NN 512
#define NC 128

// logit scratch (4 MB)
__device__ float g_logits[NB * NN * NN];

__device__ __forceinline__ uint32_t f2tf32(float f) {
    uint32_t r;
    asm("cvt.rna.tf32.f32 %0, %1;" : "=r"(r) : "f"(f));
    return r;
}
__device__ __forceinline__ float lrelu(float v) { return v > 0.f ? v : 0.01f * v; }

// D(16x8,f32) += A(16x8,tf32,row) * B(8x8,tf32,col)
__device__ __forceinline__ void mma8(float* d, uint32_t a0, uint32_t a1, uint32_t a2, uint32_t a3,
                                     uint32_t b0, uint32_t b1) {
    asm volatile("mma.sync.aligned.m16n8k8.row.col.f32.tf32.tf32.f32 "
                 "{%0,%1,%2,%3},{%4,%5,%6,%7},{%8,%9},{%0,%1,%2,%3};"
                 : "+f"(d[0]), "+f"(d[1]), "+f"(d[2]), "+f"(d[3])
                 : "r"(a0), "r"(a1), "r"(a2), "r"(a3), "r"(b0), "r"(b1));
}

// One MLP layer on a 128-row edge tile.
//   aIn : SMEM activations, tf32 bits, [128][K+4]
//   aOut: SMEM activations out, tf32 bits, [128][N+4]  (bias + lrelu applied)
//   Wg  : gmem weights [N][K] row-major fp32
//   sW  : SMEM weight chunk buffer [N][20] (KC=16 + pad4)
// 16 warps: warp_m = wid&3 (32 rows), warp_n = wid>>2 (N/4 cols).
template <int N, int K>
__device__ void layer(const uint32_t* __restrict__ aIn, uint32_t* __restrict__ aOut,
                      const float* __restrict__ Wg, const float* __restrict__ bias,
                      uint32_t* __restrict__ sW, int tid)
{
    constexpr int SA = K + 4;
    constexpr int SO = N + 4;
    constexpr int NT = N / 32;        // n-tiles (8 wide) per warp
    constexpr int NCH = K / 16;       // weight chunks
    constexpr int PW = (N * 16) / 512;// staged words per thread per chunk

    const int wid = tid >> 5, lane = tid & 31;
    const int g = lane >> 2, t = lane & 3;
    const int mb = (wid & 3) * 32;
    const int nwb = (wid >> 2) * (N / 4);

    float d[2][NT][4];
#pragma unroll
    for (int mt = 0; mt < 2; ++mt)
#pragma unroll
        for (int nt = 0; nt < NT; ++nt)
#pragma unroll
            for (int q = 0; q < 4; ++q) d[mt][nt][q] = 0.f;

    // stage chunk 0
    float wpre[PW];
#pragma unroll
    for (int p = 0; p < PW; ++p) {
        int idx = tid + p * 512, n = idx >> 4, kk = idx & 15;
        wpre[p] = Wg[n * K + kk];
    }
#pragma unroll
    for (int p = 0; p < PW; ++p) {
        int idx = tid + p * 512, n = idx >> 4, kk = idx & 15;
        sW[n * 20 + kk] = f2tf32(wpre[p]);
    }
    __syncthreads();

    for (int c = 0; c < NCH; ++c) {
        if (c + 1 < NCH) {      // prefetch next chunk into registers (hides L2 latency)
#pragma unroll
            for (int p = 0; p < PW; ++p) {
                int idx = tid + p * 512, n = idx >> 4, kk = idx & 15;
                wpre[p] = Wg[n * K + (c + 1) * 16 + kk];
            }
        }
#pragma unroll
        for (int ks = 0; ks < 2; ++ks) {
            const int kks = ks * 8;
            uint32_t bf[NT][2];
#pragma unroll
            for (int nt = 0; nt < NT; ++nt) {
                int n = nwb + nt * 8 + g;
                bf[nt][0] = sW[n * 20 + kks + t];
                bf[nt][1] = sW[n * 20 + kks + t + 4];
            }
#pragma unroll
            for (int mt = 0; mt < 2; ++mt) {
                const int r0 = mb + mt * 16 + g;
                const int ka = c * 16 + kks + t;
                uint32_t a0 = aIn[r0 * SA + ka];
                uint32_t a1 = aIn[(r0 + 8) * SA + ka];
                uint32_t a2 = aIn[r0 * SA + ka + 4];
                uint32_t a3 = aIn[(r0 + 8) * SA + ka + 4];
#pragma unroll
                for (int nt = 0; nt < NT; ++nt)
                    mma8(d[mt][nt], a0, a1, a2, a3, bf[nt][0], bf[nt][1]);
            }
        }
        __syncthreads();
        if (c + 1 < NCH) {
#pragma unroll
            for (int p = 0; p < PW; ++p) {
                int idx = tid + p * 512, n = idx >> 4, kk = idx & 15;
                sW[n * 20 + kk] = f2tf32(wpre[p]);
            }
            __syncthreads();
        }
    }

    // epilogue: bias + lrelu + tf32-quantize, store transposed-free [row][col]
#pragma unroll
    for (int mt = 0; mt < 2; ++mt) {
        const int r0 = mb + mt * 16 + g;
#pragma unroll
        for (int nt = 0; nt < NT; ++nt) {
            const int cb = nwb + nt * 8 + 2 * t;
            float bb0 = bias[cb], bb1 = bias[cb + 1];
            uint32_t v0 = f2tf32(lrelu(d[mt][nt][0] + bb0));
            uint32_t v1 = f2tf32(lrelu(d[mt][nt][1] + bb1));
            uint32_t v2 = f2tf32(lrelu(d[mt][nt][2] + bb0));
            uint32_t v3 = f2tf32(lrelu(d[mt][nt][3] + bb1));
            *(uint2*)(aOut + r0 * SO + cb)       = make_uint2(v0, v1);
            *(uint2*)(aOut + (r0 + 8) * SO + cb) = make_uint2(v2, v3);
        }
    }
    __syncthreads();
}

extern __shared__ float dynsm[];

__global__ void __launch_bounds__(512, 1)
mlp_kernel(const float* __restrict__ x,
           const float* __restrict__ w1, const float* __restrict__ b1,
           const float* __restrict__ w2, const float* __restrict__ b2,
           const float* __restrict__ w3, const float* __restrict__ b3,
           const float* __restrict__ w4, const float* __restrict__ b4,
           const float* __restrict__ w5, const float* __restrict__ b5)
{
    __shared__ float sXi[NC];
    __shared__ float sBias[576];   // b1[192] b2[192] b3[96] b4[96]
    __shared__ float sW5[96];
    __shared__ float sB5;

    const int tid = threadIdx.x;

    // block -> (b, i, jt) over symmetric 128-tiles: jt >= block(i)
    int blk = blockIdx.x;
    int b = blk / 1280;
    int t = blk - b * 1280;
    int ib, local, cnt;
    if (t < 512)       { ib = 0; local = t;        cnt = 4; }
    else if (t < 896)  { ib = 1; local = t - 512;  cnt = 3; }
    else if (t < 1152) { ib = 2; local = t - 896;  cnt = 2; }
    else               { ib = 3; local = t - 1152; cnt = 1; }
    const int i  = ib * 128 + local / cnt;
    const int jt = ib + local % cnt;
    const int j0 = jt * 128;

    const float* xb = x + (size_t)b * NN * NC;

    uint32_t* bufA = (uint32_t*)dynsm;        // 128*196 words
    uint32_t* bufB = bufA + 128 * 196;        // 128*196 words
    uint32_t* sW   = bufB + 128 * 196;        // 192*20 words

    // stage per-CTA constants
    if (tid < 128) sXi[tid] = xb[(size_t)i * NC + tid];
    if (tid < 192) { sBias[tid] = b1[tid]; sBias[192 + tid] = b2[tid]; }
    if (tid < 96)  { sBias[384 + tid] = b3[tid]; sBias[480 + tid] = b4[tid]; sW5[tid] = w5[tid]; }
    if (tid == 0)  sB5 = b5[0];
    __syncthreads();

    // prologue: bufA[r][k] = tf32(|x_i[k] - x_{j0+r}[k]|), stride 132
    for (int idx = tid; idx < 128 * 128; idx += 512) {
        int r = idx >> 7, k = idx & 127;
        float v = fabsf(sXi[k] - xb[(size_t)(j0 + r) * NC + k]);
        bufA[r * 132 + k] = f2tf32(v);
    }
    __syncthreads();

    layer<192, 128>(bufA, bufB, w1, sBias + 0,   sW, tid);
    layer<192, 192>(bufB, bufA, w2, sBias + 192, sW, tid);
    layer<96, 192> (bufA, bufB, w3, sBias + 384, sW, tid);
    layer<96, 96>  (bufB, bufA, w4, sBias + 480, sW, tid);

    // layer 5: 96 -> 1 (no activation), 4 threads per row
    {
        const int r = tid >> 2, q = tid & 3;
        const uint32_t* arow = bufA + r * 100 + q * 24;
        float acc = 0.f;
#pragma unroll
        for (int k = 0; k < 24; ++k)
            acc = fmaf(__uint_as_float(arow[k]), sW5[q * 24 + k], acc);
        acc += __shfl_xor_sync(0xffffffffu, acc, 1);
        acc += __shfl_xor_sync(0xffffffffu, acc, 2);
        if (q == 0) {
            float lg = acc + sB5;
            int j = j0 + r;
            g_logits[((size_t)b * NN + i) * NN + j] = lg;   // direct
            g_logits[((size_t)b * NN + j) * NN + i] = lg;   // mirror (d symmetric)
        }
    }
}

__global__ void __launch_bounds__(256)
softmax_kernel(float2* __restrict__ out)
{
    __shared__ float sred[8];
    __shared__ float sval;
    int row = blockIdx.x;        // b*NN + i
    int i   = row & (NN - 1);
    const float* L = g_logits + (size_t)row * NN;
    int tid  = threadIdx.x;
    int lane = tid & 31, warp = tid >> 5;

    float l0 = L[tid];
    float l1 = L[tid + 256];
    if (tid == i)       l0 -= 1e8f;
    if (tid + 256 == i) l1 -= 1e8f;

    float m = fmaxf(l0, l1);
#pragma unroll
    for (int o = 16; o > 0; o >>= 1) m = fmaxf(m, __shfl_xor_sync(0xffffffffu, m, o));
    if (lane == 0) sred[warp] = m;
    __syncthreads();
    if (tid == 0) {
        float v = sred[0];
        for (int w = 1; w < 8; ++w) v = fmaxf(v, sred[w]);
        sval = v;
    }
    __syncthreads();
    float M  = sval;
    float e0 = expf(l0 - M);
    float e1 = expf(l1 - M);
    float s  = e0 + e1;
#pragma unroll
    for (int o = 16; o > 0; o >>= 1) s += __shfl_xor_sync(0xffffffffu, s, o);
    __syncthreads();
    if (lane == 0) sred[warp] = s;
    __syncthreads();
    if (tid == 0) {
        float v = 0.f;
        for (int w = 0; w < 8; ++w) v += sred[w];
        sval = 1.0f / v;
    }
    __syncthreads();
    float inv = sval;

    float2* o2 = out + (size_t)row * NN;
    o2[tid]       = make_float2(tid == i ? 1.f : 0.f,       e0 * inv);
    o2[tid + 256] = make_float2(tid + 256 == i ? 1.f : 0.f, e1 * inv);
}

extern "C" void kernel_launch(void* const* d_in, const int* in_sizes, int n_in,
                              void* d_out, int out_size)
{
    const float* x  = (const float*)d_in[0];
    // d_in[1] = W_id (exact identity; regenerated analytically)
    const float* w1 = (const float*)d_in[2];
    const float* b1 = (const float*)d_in[3];
    const float* w2 = (const float*)d_in[4];
    const float* b2 = (const float*)d_in[5];
    const float* w3 = (const float*)d_in[6];
    const float* b3 = (const float*)d_in[7];
    const float* w4 = (const float*)d_in[8];
    const float* b4 = (const float*)d_in[9];
    const float* w5 = (const float*)d_in[10];
    const float* b5 = (const float*)d_in[11];
    float2* out = (float2*)d_out;

    // dyn smem: 2 act buffers (128x196) + weight chunk (192x20) = 216,064 B
    size_t smem_bytes = (2 * 128 * 196 + 192 * 20) * sizeof(float);
    cudaFuncSetAttribute(mlp_kernel, cudaFuncAttributeMaxDynamicSharedMemorySize,
                         (int)smem_bytes);

    mlp_kernel<<<NB * 1280, 512, smem_bytes>>>(
        x, w1, b1, w2, b2, w3, b3, w4, b4, w5, b5);
    softmax_kernel<<<NB * NN, 256>>>(out);
}

// round 4
// speedup vs baseline: 6.1295x; 1.0469x over previous
#include <cuda_runtime.h>
#include <cstdint>
#include <math.h>

#define NB 4
#define NN 512
#define NC 128

// logit scratch (4 MB)
__device__ float g_logits[NB * NN * NN];

__device__ __forceinline__ uint32_t f2tf32(float f) {
    uint32_t r;
    asm("cvt.rna.tf32.f32 %0, %1;" : "=r"(r) : "f"(f));
    return r;
}
__device__ __forceinline__ float lrelu(float v) { return v > 0.f ? v : 0.01f * v; }
__device__ __forceinline__ uint32_t smem_u32(const void* p) {
    uint32_t a;
    asm("{ .reg .u64 t; cvta.to.shared.u64 t, %1; cvt.u32.u64 %0, t; }" : "=r"(a) : "l"(p));
    return a;
}

// D(16x8,f32) += A(16x8,tf32,row) * B(8x8,tf32,col)
__device__ __forceinline__ void mma8(float* d, uint32_t a0, uint32_t a1, uint32_t a2, uint32_t a3,
                                     uint32_t b0, uint32_t b1) {
    asm volatile("mma.sync.aligned.m16n8k8.row.col.f32.tf32.tf32.f32 "
                 "{%0,%1,%2,%3},{%4,%5,%6,%7},{%8,%9},{%0,%1,%2,%3};"
                 : "+f"(d[0]), "+f"(d[1]), "+f"(d[2]), "+f"(d[3])
                 : "r"(a0), "r"(a1), "r"(a2), "r"(a3), "r"(b0), "r"(b1));
}

// permuted position of k within a 32-k chunk: thread t owns words t*8..t*8+7 = k = t,t+4,...,t+28
__device__ __forceinline__ int perm32(int kk) { return (kk & 3) * 8 + (kk >> 2); }

#define CP_ASYNC4(dst_u32, src_ptr) \
    asm volatile("cp.async.ca.shared.global [%0], [%1], 4;" :: "r"(dst_u32), "l"(src_ptr) : "memory")
#define CP_COMMIT() asm volatile("cp.async.commit_group;" ::: "memory")
#define CP_WAIT0()  asm volatile("cp.async.wait_group 0;" ::: "memory")

// Stage chunk0 of W[N][K] (32 k's) into sW (stride 36 words, permuted) via cp.async.
__device__ __forceinline__ void stage0_async(const float* __restrict__ Wg, int N, int K,
                                             uint32_t sw_bytes, int tid) {
    int PW = N >> 4;
    for (int p = 0; p < PW; ++p) {
        int idx = tid + (p << 9);
        int n = idx >> 5, kk = idx & 31;
        CP_ASYNC4(sw_bytes + (uint32_t)((n * 36 + perm32(kk)) * 4), Wg + n * K + kk);
    }
    CP_COMMIT();
}

// One MLP layer, in-place on `buf` (input stride SA words, output stride SO words, both permuted).
// Weight chunks (KC=32) double-buffered in sWa/sWb via cp.async.
// 16 warps: warp_m = wid&3 (32 rows), warp_n = wid>>2 (N/4 cols). Requires chunk0 staged in sWa.
template <int N, int K, int SA, int SO>
__device__ void layer(uint32_t* __restrict__ buf,
                      const float* __restrict__ Wg, const float* __restrict__ bias,
                      uint32_t* __restrict__ sWa, uint32_t* __restrict__ sWb,
                      uint32_t swa_bytes, uint32_t swb_bytes, int tid)
{
    constexpr int NT  = N / 32;   // 8-wide n-tiles per warp
    constexpr int NCH = K / 32;   // 32-k chunks
    constexpr int PW  = N / 16;   // cp.async ops per thread per chunk

    const int wid = tid >> 5, lane = tid & 31;
    const int g = lane >> 2, t = lane & 3;
    const int mb  = (wid & 3) * 32;
    const int nwb = (wid >> 2) * (N / 4);

    float d[2][NT][4];
#pragma unroll
    for (int mt = 0; mt < 2; ++mt)
#pragma unroll
        for (int nt = 0; nt < NT; ++nt)
#pragma unroll
            for (int q = 0; q < 4; ++q) d[mt][nt][q] = 0.f;

    for (int c = 0; c < NCH; ++c) {
        // async-stage chunk c+1 into the other buffer (overlaps with MMAs below)
        if (c + 1 < NCH) {
            uint32_t dstb = ((c + 1) & 1) ? swb_bytes : swa_bytes;
            const float* src = Wg + (c + 1) * 32;
#pragma unroll
            for (int p = 0; p < PW; ++p) {
                int idx = tid + (p << 9);
                int n = idx >> 5, kk = idx & 31;
                CP_ASYNC4(dstb + (uint32_t)((n * 36 + perm32(kk)) * 4), src + n * K + kk);
            }
            CP_COMMIT();
        }
        const uint32_t* sWc = (c & 1) ? sWb : sWa;
#pragma unroll
        for (int h = 0; h < 2; ++h) {
            uint32_t bf[NT][4];
#pragma unroll
            for (int nt = 0; nt < NT; ++nt) {
                int n = nwb + nt * 8 + g;
                *(uint4*)bf[nt] = *(const uint4*)(sWc + n * 36 + t * 8 + 4 * h);
            }
            uint32_t av[2][2][4];
#pragma unroll
            for (int mt = 0; mt < 2; ++mt) {
                int r0 = mb + mt * 16 + g;
                *(uint4*)av[mt][0] = *(const uint4*)(buf + r0 * SA + c * 32 + t * 8 + 4 * h);
                *(uint4*)av[mt][1] = *(const uint4*)(buf + (r0 + 8) * SA + c * 32 + t * 8 + 4 * h);
            }
#pragma unroll
            for (int ks = 0; ks < 2; ++ks)
#pragma unroll
                for (int mt = 0; mt < 2; ++mt)
#pragma unroll
                    for (int nt = 0; nt < NT; ++nt)
                        mma8(d[mt][nt],
                             av[mt][0][2 * ks], av[mt][1][2 * ks],
                             av[mt][0][2 * ks + 1], av[mt][1][2 * ks + 1],
                             bf[nt][2 * ks], bf[nt][2 * ks + 1]);
        }
        if (c + 1 < NCH) CP_WAIT0();
        __syncthreads();
    }

    // epilogue: bias + lrelu + tf32, write IN PLACE (input is dead after last sync), permuted
#pragma unroll
    for (int mt = 0; mt < 2; ++mt) {
        int r0 = mb + mt * 16 + g;
#pragma unroll
        for (int nt = 0; nt < NT; ++nt) {
            int cb = nwb + nt * 8 + 2 * t;
            float bb0 = bias[cb], bb1 = bias[cb + 1];
            int w0 = (cb >> 5) * 32 + perm32(cb & 31);
            int w1 = ((cb + 1) >> 5) * 32 + perm32((cb + 1) & 31);
            buf[r0 * SO + w0]       = f2tf32(lrelu(d[mt][nt][0] + bb0));
            buf[r0 * SO + w1]       = f2tf32(lrelu(d[mt][nt][1] + bb1));
            buf[(r0 + 8) * SO + w0] = f2tf32(lrelu(d[mt][nt][2] + bb0));
            buf[(r0 + 8) * SO + w1] = f2tf32(lrelu(d[mt][nt][3] + bb1));
        }
    }
    // caller stages next chunk0 and syncs
}

extern __shared__ uint32_t dynsm[];

__global__ void __launch_bounds__(512, 1)
mlp_kernel(const float* __restrict__ x,
           const float* __restrict__ w1, const float* __restrict__ b1,
           const float* __restrict__ w2, const float* __restrict__ b2,
           const float* __restrict__ w3, const float* __restrict__ b3,
           const float* __restrict__ w4, const float* __restrict__ b4,
           const float* __restrict__ w5, const float* __restrict__ b5)
{
    __shared__ float sXi[NC];
    __shared__ float sBias[576];   // b1[192] b2[192] b3[96] b4[96]
    __shared__ float sW5[96];
    __shared__ float sB5;

    const int tid = threadIdx.x;

    // block -> (b, i, jt) over symmetric 128-tiles: jt >= block(i)
    int blk = blockIdx.x;
    int b = blk / 1280;
    int t = blk - b * 1280;
    int ib, local, cnt;
    if (t < 512)       { ib = 0; local = t;        cnt = 4; }
    else if (t < 896)  { ib = 1; local = t - 512;  cnt = 3; }
    else if (t < 1152) { ib = 2; local = t - 896;  cnt = 2; }
    else               { ib = 3; local = t - 1152; cnt = 1; }
    const int i  = ib * 128 + local / cnt;
    const int jt = ib + local % cnt;
    const int j0 = jt * 128;

    const float* xb = x + (size_t)b * NN * NC;

    uint32_t* buf = dynsm;                 // 128*196 words, in-place across layers
    uint32_t* sWa = buf + 128 * 196;       // 192*36 words
    uint32_t* sWb = sWa + 192 * 36;        // 192*36 words
    const uint32_t swa_bytes = smem_u32(sWa);
    const uint32_t swb_bytes = smem_u32(sWb);

    // per-CTA constants
    if (tid < 128) sXi[tid] = xb[(size_t)i * NC + tid];
    if (tid < 192) { sBias[tid] = b1[tid]; sBias[192 + tid] = b2[tid]; }
    if (tid < 96)  { sBias[384 + tid] = b3[tid]; sBias[480 + tid] = b4[tid]; sW5[tid] = w5[tid]; }
    if (tid == 0)  sB5 = b5[0];
    __syncthreads();   // sXi ready before prologue uses it

    // stage w1 chunk0 while doing the prologue
    stage0_async(w1, 192, 128, swa_bytes, tid);

    // prologue: buf[r][k] = tf32(|x_i[k] - x_{j0+r}[k]|), stride 132, permuted
    for (int idx = tid; idx < 128 * 128; idx += 512) {
        int r = idx >> 7, k = idx & 127;
        float v = fabsf(sXi[k] - xb[(size_t)(j0 + r) * NC + k]);
        buf[r * 132 + (k >> 5) * 32 + perm32(k & 31)] = f2tf32(v);
    }
    CP_WAIT0();
    __syncthreads();

    layer<192, 128, 132, 196>(buf, w1, sBias + 0,   sWa, sWb, swa_bytes, swb_bytes, tid);
    stage0_async(w2, 192, 192, swa_bytes, tid); CP_WAIT0(); __syncthreads();
    layer<192, 192, 196, 196>(buf, w2, sBias + 192, sWa, sWb, swa_bytes, swb_bytes, tid);
    stage0_async(w3, 96, 192, swa_bytes, tid);  CP_WAIT0(); __syncthreads();
    layer<96, 192, 196, 100>(buf, w3, sBias + 384, sWa, sWb, swa_bytes, swb_bytes, tid);
    stage0_async(w4, 96, 96, swa_bytes, tid);   CP_WAIT0(); __syncthreads();
    layer<96, 96, 100, 100>(buf, w4, sBias + 480, sWa, sWb, swa_bytes, swb_bytes, tid);
    __syncthreads();

    // layer 5: 96 -> 1 (no activation); 4 threads per row, permuted reads
    {
        const int r = tid >> 2, q = tid & 3;
        const uint32_t* arow = buf + r * 100;
        float acc = 0.f;
#pragma unroll
        for (int k = 0; k < 24; ++k) {
            int col = q * 24 + k;
            int w = (col >> 5) * 32 + perm32(col & 31);
            acc = fmaf(__uint_as_float(arow[w]), sW5[col], acc);
        }
        acc += __shfl_xor_sync(0xffffffffu, acc, 1);
        acc += __shfl_xor_sync(0xffffffffu, acc, 2);
        if (q == 0) {
            float lg = acc + sB5;
            int j = j0 + r;
            g_logits[((size_t)b * NN + i) * NN + j] = lg;   // direct
            g_logits[((size_t)b * NN + j) * NN + i] = lg;   // mirror (d symmetric)
        }
    }
}

__global__ void __launch_bounds__(256)
softmax_kernel(float2* __restrict__ out)
{
    __shared__ float sred[8];
    __shared__ float sval;
    int row = blockIdx.x;        // b*NN + i
    int i   = row & (NN - 1);
    const float* L = g_logits + (size_t)row * NN;
    int tid  = threadIdx.x;
    int lane = tid & 31, warp = tid >> 5;

    float l0 = L[tid];
    float l1 = L[tid + 256];
    if (tid == i)       l0 -= 1e8f;
    if (tid + 256 == i) l1 -= 1e8f;

    float m = fmaxf(l0, l1);
#pragma unroll
    for (int o = 16; o > 0; o >>= 1) m = fmaxf(m, __shfl_xor_sync(0xffffffffu, m, o));
    if (lane == 0) sred[warp] = m;
    __syncthreads();
    if (tid == 0) {
        float v = sred[0];
        for (int w = 1; w < 8; ++w) v = fmaxf(v, sred[w]);
        sval = v;
    }
    __syncthreads();
    float M  = sval;
    float e0 = expf(l0 - M);
    float e1 = expf(l1 - M);
    float s  = e0 + e1;
#pragma unroll
    for (int o = 16; o > 0; o >>= 1) s += __shfl_xor_sync(0xffffffffu, s, o);
    __syncthreads();
    if (lane == 0) sred[warp] = s;
    __syncthreads();
    if (tid == 0) {
        float v = 0.f;
        for (int w = 0; w < 8; ++w) v += sred[w];
        sval = 1.0f / v;
    }
    __syncthreads();
    float inv = sval;

    float2* o2 = out + (size_t)row * NN;
    o2[tid]       = make_float2(tid == i ? 1.f : 0.f,       e0 * inv);
    o2[tid + 256] = make_float2(tid + 256 == i ? 1.f : 0.f, e1 * inv);
}

extern "C" void kernel_launch(void* const* d_in, const int* in_sizes, int n_in,
                              void* d_out, int out_size)
{
    const float* x  = (const float*)d_in[0];
    // d_in[1] = W_id (exact identity; regenerated analytically)
    const float* w1 = (const float*)d_in[2];
    const float* b1 = (const float*)d_in[3];
    const float* w2 = (const float*)d_in[4];
    const float* b2 = (const float*)d_in[5];
    const float* w3 = (const float*)d_in[6];
    const float* b3 = (const float*)d_in[7];
    const float* w4 = (const float*)d_in[8];
    const float* b4 = (const float*)d_in[9];
    const float* w5 = (const float*)d_in[10];
    const float* b5 = (const float*)d_in[11];
    float2* out = (float2*)d_out;

    // dyn smem: act buf 128x196 + 2 weight chunk buffers 192x36  = 155,648 B
    size_t smem_bytes = (128 * 196 + 2 * 192 * 36) * sizeof(uint32_t);
    cudaFuncSetAttribute(mlp_kernel, cudaFuncAttributeMaxDynamicSharedMemorySize,
                         (int)smem_bytes);

    mlp_kernel<<<NB * 1280, 512, smem_bytes>>>(
        x, w1, b1, w2, b2, w3, b3, w4, b4, w5, b5);
    softmax_kernel<<<NB * NN, 256>>>(out);
}